// round 15
// baseline (speedup 1.0000x reference)
#include <cuda_runtime.h>
#include <cuda_fp16.h>
#include <math.h>
#include <stdint.h>

// ---------------------------------------------------------------------------
// Problem constants
// ---------------------------------------------------------------------------
#define BSZ    8
#define TLEN   2048
#define HID    1024
#define STATE  256
#define FFNDIM 4096
#define MROWS  (BSZ*TLEN)          // 16384
#define CHUNK  512                 // scan steps per pipeline chunk
#define NCHUNK (TLEN / CHUNK)      // 4

// Scratch (device globals: allocation-free rule)
__device__ float g_xB[MROWS*STATE];      //  16 MB
__device__ float g_xD[MROWS*HID];        //  64 MB (reused as pre-LN r)
__device__ float g_states[MROWS*STATE];  //  16 MB
__device__ float g_yln[MROWS*HID];       //  64 MB
__device__ float g_h[MROWS*FFNDIM];      // 256 MB
__device__ float g_carry[BSZ*STATE];     // scan state carry between chunks

__device__ __forceinline__ float gelu_exact(float v) {
    return 0.5f * v * (1.0f + erff(v * 0.70710678118654752f));
}

__device__ __forceinline__ uint32_t smem_u32(const void* p) {
    uint32_t a;
    asm("{ .reg .u64 t; cvta.to.shared.u64 t, %1; cvt.u32.u64 %0, t; }"
        : "=r"(a) : "l"(p));
    return a;
}

// ---- packed f32x2 helpers --------------------------------------------------
__device__ __forceinline__ uint64_t pk2(float x, float y) {
    uint64_t r;
    asm("mov.b64 %0, {%1, %2};" : "=l"(r) : "f"(x), "f"(y));
    return r;
}
__device__ __forceinline__ void upk2(uint64_t v, float& x, float& y) {
    asm("mov.b64 {%0, %1}, %2;" : "=f"(x), "=f"(y) : "l"(v));
}
__device__ __forceinline__ uint64_t fma2(uint64_t a, uint64_t b, uint64_t c) {
    uint64_t d;
    asm("fma.rn.f32x2 %0, %1, %2, %3;" : "=l"(d) : "l"(a), "l"(b), "l"(c));
    return d;
}

__device__ __forceinline__ void ldsm4(uint32_t addr, uint32_t r[4]) {
    asm volatile("ldmatrix.sync.aligned.m8n8.x4.shared.b16 {%0,%1,%2,%3}, [%4];"
                 : "=r"(r[0]), "=r"(r[1]), "=r"(r[2]), "=r"(r[3]) : "r"(addr));
}

__device__ __forceinline__ void mma16816(float c[4], const uint32_t a[4],
                                         uint32_t b0, uint32_t b1) {
    asm volatile(
        "mma.sync.aligned.m16n8k16.row.col.f32.f16.f16.f32 "
        "{%0,%1,%2,%3}, {%4,%5,%6,%7}, {%8,%9}, {%0,%1,%2,%3};"
        : "+f"(c[0]), "+f"(c[1]), "+f"(c[2]), "+f"(c[3])
        : "r"(a[0]), "r"(a[1]), "r"(a[2]), "r"(a[3]), "r"(b0), "r"(b1));
}

// ---------------------------------------------------------------------------
// fp16-split (3-pass) tensor-core GEMM body (device function; known-good):
//   C[row0:+128, col0:+128] = A[M,K] @ B[N,K]^T (+bias)(gelu)(+add1)(+add2)
// ---------------------------------------------------------------------------
#define GH_STRIDE_B 80
#define GH_TILE_B   (128 * GH_STRIDE_B)
#define GH_AB 0
#define GH_AS (1 * GH_TILE_B)
#define GH_BB (2 * GH_TILE_B)
#define GH_BS (3 * GH_TILE_B)
#define GH_STAGE (4 * GH_TILE_B)
#define GH_DYN_SMEM (2 * GH_STAGE)

__device__ void gemm_dev(
    const float* __restrict__ A, const float* __restrict__ B,
    float* __restrict__ Cmat,
    size_t row0, size_t col0, int N, int K,
    const float* __restrict__ bias, const float* add1,
    const float* add2, int do_gelu)
{
    extern __shared__ char smem[];
    const uint32_t sbase = smem_u32(smem);

    const int tid = threadIdx.x;
    const int w   = tid >> 5;
    const int l   = tid & 31;
    const int Kc  = K >> 5;

    const int rbase = tid >> 3;
    const int c4    = tid & 7;
    const float* Ap = A + (row0 + rbase) * (size_t)K + c4 * 4;
    const float* Bp = B + (col0 + rbase) * (size_t)K + c4 * 4;

    float4 ra[4], rb4[4];
#pragma unroll
    for (int i = 0; i < 4; ++i) {
        ra[i]  = *(const float4*)(Ap + (size_t)(32 * i) * K);
        rb4[i] = *(const float4*)(Bp + (size_t)(32 * i) * K);
    }

    const uint32_t stoff = (uint32_t)rbase * GH_STRIDE_B + (uint32_t)c4 * 8;

#define CVST(sidx)                                                             \
    do {                                                                       \
        char* pAb = smem + (sidx) * GH_STAGE + GH_AB;                          \
        char* pAs = smem + (sidx) * GH_STAGE + GH_AS;                          \
        char* pBb = smem + (sidx) * GH_STAGE + GH_BB;                          \
        char* pBs = smem + (sidx) * GH_STAGE + GH_BS;                          \
        _Pragma("unroll")                                                      \
        for (int i = 0; i < 4; ++i) {                                          \
            uint32_t off = stoff + (uint32_t)i * (32u * GH_STRIDE_B);          \
            union { __half2 h2[2]; uint2 u; } pk;                              \
            __half2 hb0 = __floats2half2_rn(ra[i].x, ra[i].y);                 \
            __half2 hb1 = __floats2half2_rn(ra[i].z, ra[i].w);                 \
            float2 f0 = __half22float2(hb0), f1 = __half22float2(hb1);         \
            pk.h2[0] = hb0; pk.h2[1] = hb1;                                    \
            *(uint2*)(pAb + off) = pk.u;                                       \
            pk.h2[0] = __floats2half2_rn(ra[i].x - f0.x, ra[i].y - f0.y);      \
            pk.h2[1] = __floats2half2_rn(ra[i].z - f1.x, ra[i].w - f1.y);      \
            *(uint2*)(pAs + off) = pk.u;                                       \
            hb0 = __floats2half2_rn(rb4[i].x, rb4[i].y);                       \
            hb1 = __floats2half2_rn(rb4[i].z, rb4[i].w);                       \
            f0 = __half22float2(hb0); f1 = __half22float2(hb1);                \
            pk.h2[0] = hb0; pk.h2[1] = hb1;                                    \
            *(uint2*)(pBb + off) = pk.u;                                       \
            pk.h2[0] = __floats2half2_rn(rb4[i].x - f0.x, rb4[i].y - f0.y);    \
            pk.h2[1] = __floats2half2_rn(rb4[i].z - f1.x, rb4[i].w - f1.y);    \
            *(uint2*)(pBs + off) = pk.u;                                       \
        }                                                                      \
    } while (0)

    CVST(0);
    __syncthreads();

    const int m0 = (w & 3) * 32;
    const int n0 = (w >> 2) * 64;
    const int rA = l & 15;
    const int qA = l >> 4;
    const int rB = (l & 7) | ((l & 16) >> 1);
    const int qB = (l >> 3) & 1;

    float acc[2][8][4];
#pragma unroll
    for (int mi = 0; mi < 2; ++mi)
#pragma unroll
        for (int ni = 0; ni < 8; ++ni)
#pragma unroll
            for (int q = 0; q < 4; ++q) acc[mi][ni][q] = 0.f;

    for (int kt = 0; kt < Kc; ++kt) {
        if (kt + 1 < Kc) {
            const float* Ap2 = Ap + (kt + 1) * 32;
            const float* Bp2 = Bp + (kt + 1) * 32;
#pragma unroll
            for (int i = 0; i < 4; ++i) {
                ra[i]  = *(const float4*)(Ap2 + (size_t)(32 * i) * K);
                rb4[i] = *(const float4*)(Bp2 + (size_t)(32 * i) * K);
            }
        }

        const uint32_t stb = sbase + (uint32_t)(kt & 1) * GH_STAGE;
#pragma unroll
        for (int kk = 0; kk < 2; ++kk) {
            const int q0 = kk * 2;
            uint32_t ab[2][4], as2[2][4], bb[4][4];
            const uint32_t aoff =
                (uint32_t)(m0 + rA) * GH_STRIDE_B + (uint32_t)(q0 + qA) * 16;
            const uint32_t boff =
                (uint32_t)(n0 + rB) * GH_STRIDE_B + (uint32_t)(q0 + qB) * 16;

            ldsm4(stb + GH_AB + aoff, ab[0]);
            ldsm4(stb + GH_AB + aoff + 16u * GH_STRIDE_B, ab[1]);
            ldsm4(stb + GH_AS + aoff, as2[0]);
            ldsm4(stb + GH_AS + aoff + 16u * GH_STRIDE_B, as2[1]);
#pragma unroll
            for (int g = 0; g < 4; ++g)
                ldsm4(stb + GH_BB + boff + (uint32_t)g * (16u * GH_STRIDE_B), bb[g]);

#pragma unroll
            for (int mi = 0; mi < 2; ++mi)
#pragma unroll
                for (int g = 0; g < 4; ++g) {
                    mma16816(acc[mi][2 * g],     ab[mi], bb[g][0], bb[g][1]);
                    mma16816(acc[mi][2 * g + 1], ab[mi], bb[g][2], bb[g][3]);
                }
#pragma unroll
            for (int mi = 0; mi < 2; ++mi)
#pragma unroll
                for (int g = 0; g < 4; ++g) {
                    mma16816(acc[mi][2 * g],     as2[mi], bb[g][0], bb[g][1]);
                    mma16816(acc[mi][2 * g + 1], as2[mi], bb[g][2], bb[g][3]);
                }
#pragma unroll
            for (int g = 0; g < 4; ++g)
                ldsm4(stb + GH_BS + boff + (uint32_t)g * (16u * GH_STRIDE_B), bb[g]);
#pragma unroll
            for (int mi = 0; mi < 2; ++mi)
#pragma unroll
                for (int g = 0; g < 4; ++g) {
                    mma16816(acc[mi][2 * g],     ab[mi], bb[g][0], bb[g][1]);
                    mma16816(acc[mi][2 * g + 1], ab[mi], bb[g][2], bb[g][3]);
                }
        }

        if (kt + 1 < Kc) CVST((kt + 1) & 1);
        __syncthreads();
    }
#undef CVST

#pragma unroll
    for (int mi = 0; mi < 2; ++mi) {
        const size_t rtop = row0 + m0 + mi * 16 + (l >> 2);
#pragma unroll
        for (int ni = 0; ni < 8; ++ni) {
            const int gc = (int)col0 + n0 + ni * 8 + (l & 3) * 2;
            float bx = 0.f, by = 0.f;
            if (bias) {
                float2 bb2 = *(const float2*)(bias + gc);
                bx = bb2.x; by = bb2.y;
            }
#pragma unroll
            for (int h2i = 0; h2i < 2; ++h2i) {
                const size_t r = rtop + h2i * 8;
                float vx = acc[mi][ni][h2i * 2 + 0] + bx;
                float vy = acc[mi][ni][h2i * 2 + 1] + by;
                if (do_gelu) { vx = gelu_exact(vx); vy = gelu_exact(vy); }
                const size_t idx = r * (size_t)N + gc;
                if (add1) {
                    float2 t = *(const float2*)(add1 + idx);
                    vx += t.x; vy += t.y;
                }
                if (add2) {
                    float2 t = *(const float2*)(add2 + idx);
                    vx += t.x; vy += t.y;
                }
                float2 o; o.x = vx; o.y = vy;
                *(float2*)(Cmat + idx) = o;
            }
        }
    }
}

// Standalone GEMM kernel (used for xB)
__global__ void __launch_bounds__(256, 1) gemm_h3_kernel(
    const float* __restrict__ A, const float* __restrict__ B,
    float* __restrict__ Cmat, int M, int N, int K,
    const float* __restrict__ bias, const float* add1,
    const float* add2, int do_gelu)
{
    gemm_dev(A, B, Cmat, (size_t)blockIdx.y * 128, (size_t)blockIdx.x * 128,
             N, K, bias, add1, add2, do_gelu);
}

// ---------------------------------------------------------------------------
// Scan chunk (device function): one block per batch, 256 threads, CHUNK steps.
// (byte-identical math to R13 scan; CHUNK now 512)
// ---------------------------------------------------------------------------
#define SC_AREG   208
#define SC_ASM    12
#define SC_ASM_B  (SC_ASM * 256 * 16)          // 49152
#define SC_ST_B   (2 * 256 * 4)                // 2048
#define SC_XB_B   (2 * 8 * 256 * 4)            // 16384
#define SC_SMEM_BYTES (SC_ASM_B + SC_ST_B + SC_XB_B)   // 67584

__device__ void scan_chunk_dev(
    const float* __restrict__ Amat,
    const float* __restrict__ xB,
    float* __restrict__ states,
    float* __restrict__ carry,
    float* fs_out,
    int b, int c)
{
    extern __shared__ char ssm[];
    float4* Atail = (float4*)ssm;
    float*  st    = (float*)(ssm + SC_ASM_B);
    float*  xbsm  = (float*)(ssm + SC_ASM_B + SC_ST_B);

    const int tid = threadIdx.x;

    const float* arow = Amat + tid * STATE;
    uint64_t areg[SC_AREG / 2];
#pragma unroll
    for (int q = 0; q < SC_AREG / 4; ++q) {
        float4 a4 = *(const float4*)(arow + 4 * q);
        areg[2 * q]     = pk2(a4.x, a4.y);
        areg[2 * q + 1] = pk2(a4.z, a4.w);
    }
#pragma unroll
    for (int q = 0; q < SC_ASM; ++q)
        Atail[q * 256 + tid] = *(const float4*)(arow + SC_AREG + 4 * q);

    st[tid]       = (c == 0) ? 0.f : carry[b * STATE + tid];
    st[256 + tid] = 0.f;

    const float* xbbase =
        xB + (size_t)b * TLEN * STATE + (size_t)c * CHUNK * STATE;
    const int s0 = tid >> 6, c0 = (tid & 63) * 4;
    const int s1 = 4 + s0;
    float4 pf0 = *(const float4*)(xbbase + (size_t)s0 * STATE + c0);
    float4 pf1 = *(const float4*)(xbbase + (size_t)s1 * STATE + c0);
    *(float4*)(xbsm + s0 * 256 + c0) = pf0;
    *(float4*)(xbsm + s1 * 256 + c0) = pf1;

    float* sbp = states + (size_t)b * TLEN * STATE +
                 (size_t)c * CHUNK * STATE + tid;
    __syncthreads();

    float ttlast = 0.f;
    for (int t = 0; t < CHUNK; ++t) {
        const int buf  = t & 1;
        const int nbuf = buf ^ 1;

        const float xc = xbsm[((t >> 3) & 1) * 2048 + (t & 7) * 256 + tid];

        const float4* sp = (const float4*)(st + buf * 256);
        uint64_t a0 = pk2(0.f, 0.f), a1 = pk2(0.f, 0.f);
        uint64_t a2 = pk2(0.f, 0.f), a3 = pk2(0.f, 0.f);
#pragma unroll
        for (int q = 0; q < SC_AREG / 4; ++q) {
            float4 s4 = sp[q];
            if (q & 1) {
                a2 = fma2(areg[2 * q],     pk2(s4.x, s4.y), a2);
                a3 = fma2(areg[2 * q + 1], pk2(s4.z, s4.w), a3);
            } else {
                a0 = fma2(areg[2 * q],     pk2(s4.x, s4.y), a0);
                a1 = fma2(areg[2 * q + 1], pk2(s4.z, s4.w), a1);
            }
        }
#pragma unroll
        for (int q = 0; q < SC_ASM; ++q) {
            float4 s4 = sp[SC_AREG / 4 + q];
            float4 a4 = Atail[q * 256 + tid];
            if (q & 1) {
                a2 = fma2(pk2(a4.x, a4.y), pk2(s4.x, s4.y), a2);
                a3 = fma2(pk2(a4.z, a4.w), pk2(s4.z, s4.w), a3);
            } else {
                a0 = fma2(pk2(a4.x, a4.y), pk2(s4.x, s4.y), a0);
                a1 = fma2(pk2(a4.z, a4.w), pk2(s4.z, s4.w), a1);
            }
        }
        float l0, h0, l1, h1, l2, h2, l3, h3;
        upk2(a0, l0, h0); upk2(a1, l1, h1);
        upk2(a2, l2, h2); upk2(a3, l3, h3);
        float v = ((l0 + h0) + (l1 + h1)) + ((l2 + h2) + (l3 + h3)) + xc;

        float ax = fabsf(v);
        float e  = __expf(2.0f * ax);
        float tt = copysignf(1.0f - __fdividef(2.0f, e + 1.0f), v);

        st[nbuf * 256 + tid] = tt;
        sbp[(size_t)t * STATE] = tt;
        ttlast = tt;

        if (t < CHUNK - 8) {
            const int ph = t & 7;
            if (ph == 1) {
                const size_t base = ((size_t)(t >> 3) + 1) * 8;
                pf0 = *(const float4*)(xbbase + (base + s0) * STATE + c0);
                pf1 = *(const float4*)(xbbase + (base + s1) * STATE + c0);
            } else if (ph == 6) {
                const int cb = (((t >> 3) + 1) & 1) * 2048;
                *(float4*)(xbsm + cb + s0 * 256 + c0) = pf0;
                *(float4*)(xbsm + cb + s1 * 256 + c0) = pf1;
            }
        }

        __syncthreads();
    }

    carry[b * STATE + tid] = ttlast;
    if (c == NCHUNK - 1 && fs_out != nullptr)
        fs_out[b * STATE + tid] = ttlast;
}

// ---------------------------------------------------------------------------
// LayerNorm (device): one row, 256 threads x float4.
// ---------------------------------------------------------------------------
__device__ void ln_row_dev(const float* __restrict__ R,
                           const float* __restrict__ w,
                           const float* __restrict__ bb,
                           float* __restrict__ Y, size_t row)
{
    __shared__ float ss[8], sqq[8], mv[2];
    const int tid = threadIdx.x;
    const float4 v = ((const float4*)(R + row * HID))[tid];

    float s  = v.x + v.y + v.z + v.w;
    float sq = v.x * v.x + v.y * v.y + v.z * v.z + v.w * v.w;
#pragma unroll
    for (int o = 16; o; o >>= 1) {
        s  += __shfl_xor_sync(0xffffffffu, s, o);
        sq += __shfl_xor_sync(0xffffffffu, sq, o);
    }
    const int wid = tid >> 5, lane = tid & 31;
    if (lane == 0) { ss[wid] = s; sqq[wid] = sq; }
    __syncthreads();
    if (tid == 0) {
        float S = 0.f, Q = 0.f;
#pragma unroll
        for (int k = 0; k < 8; ++k) { S += ss[k]; Q += sqq[k]; }
        float mu  = S * (1.0f / HID);
        float var = Q * (1.0f / HID) - mu * mu;
        mv[0] = mu;
        mv[1] = rsqrtf(var + 1e-5f);
    }
    __syncthreads();
    const float mu = mv[0], inv = mv[1];
    const float4 w4 = ((const float4*)w)[tid];
    const float4 b4 = ((const float4*)bb)[tid];
    float4 o;
    o.x = (v.x - mu) * inv * w4.x + b4.x;
    o.y = (v.y - mu) * inv * w4.y + b4.y;
    o.z = (v.z - mu) * inv * w4.z + b4.z;
    o.w = (v.w - mu) * inv * w4.w + b4.w;
    ((float4*)(Y + row * HID))[tid] = o;
    __syncthreads();
}

// ---------------------------------------------------------------------------
// Union pipeline kernel. Grid = 2312 (CHUNK=512: 32 m-tiles per chunk):
//   [0,8)        scan chunk c_scan (batch = bid)
//   [8,264)      xD tiles for c_xd              (256 = 32m x 8n)
//   [264,520)    r tiles for c_r                (256)
//   [520,1032)   LayerNorm rows for c_ln        (512 blocks x 8 rows)
//   [1032,2056)  W1 gelu tiles for c_w1         (1024 = 32m x 32n)
//   [2056,2312)  W2 tiles for c_w2              (256)
// Row base of m-tile `my` in chunk c: (my>>2)*TLEN + c*CHUNK + (my&3)*128
// ---------------------------------------------------------------------------
__device__ __forceinline__ size_t prow0(int c, int my) {
    return (size_t)(my >> 2) * TLEN + (size_t)c * CHUNK + (size_t)(my & 3) * 128;
}

__global__ void __launch_bounds__(256, 1) pipe_kernel(
    const float* __restrict__ x, const float* __restrict__ Amat,
    const float* __restrict__ Cm, const float* __restrict__ D,
    const float* __restrict__ ln_w, const float* __restrict__ ln_b,
    const float* __restrict__ W1, const float* __restrict__ b1,
    const float* __restrict__ W2, const float* __restrict__ b2,
    float* __restrict__ out,
    float* xB, float* xD, float* states, float* yln, float* h,
    float* carry, float* fsp,
    int c_scan, int c_r, int c_ln, int c_w1, int c_w2)
{
    int bid = blockIdx.x;

    if (bid < 8) {
        if (c_scan >= 0)
            scan_chunk_dev(Amat, xB, states, carry, fsp, bid, c_scan);
        return;
    }
    bid -= 8;
    if (bid < 256) {                       // xD = x @ D^T (chunk rows)
        if (c_scan >= 0)
            gemm_dev(x, D, xD, prow0(c_scan, bid >> 3),
                     (size_t)(bid & 7) * 128, HID, HID,
                     nullptr, nullptr, nullptr, 0);
        return;
    }
    bid -= 256;
    if (bid < 256) {                       // r = states @ C^T + xD + x
        if (c_r >= 0)
            gemm_dev(states, Cm, xD, prow0(c_r, bid >> 3),
                     (size_t)(bid & 7) * 128, HID, STATE,
                     nullptr, xD, x, 0);
        return;
    }
    bid -= 256;
    if (bid < 512) {                       // LayerNorm: 8 rows per block
        if (c_ln >= 0) {
#pragma unroll 1
            for (int k = 0; k < 8; ++k) {
                int j = bid * 8 + k;       // 0..4095 within chunk
                size_t row = (size_t)(j >> 9) * TLEN +
                             (size_t)c_ln * CHUNK + (j & 511);
                ln_row_dev(xD, ln_w, ln_b, yln, row);
            }
        }
        return;
    }
    bid -= 512;
    if (bid < 1024) {                      // h = gelu(yln @ W1^T + b1)
        if (c_w1 >= 0)
            gemm_dev(yln, W1, h, prow0(c_w1, bid >> 5),
                     (size_t)(bid & 31) * 128, FFNDIM, HID,
                     b1, nullptr, nullptr, 1);
        return;
    }
    bid -= 1024;
    {                                      // y = yln + h @ W2^T + b2
        if (c_w2 >= 0)
            gemm_dev(h, W2, out, prow0(c_w2, bid >> 3),
                     (size_t)(bid & 7) * 128, HID, FFNDIM,
                     b2, yln, nullptr, 0);
    }
}

// ---------------------------------------------------------------------------
// Launch: xB GEMM, then NCHUNK+4 = 8 pipelined union launches.
// ---------------------------------------------------------------------------
extern "C" void kernel_launch(void* const* d_in, const int* in_sizes, int n_in,
                              void* d_out, int out_size)
{
    const float* x    = (const float*)d_in[0];
    const float* Amat = (const float*)d_in[1];
    const float* Bm   = (const float*)d_in[2];
    const float* Cm   = (const float*)d_in[3];
    const float* D    = (const float*)d_in[4];
    const float* ln_w = (const float*)d_in[5];
    const float* ln_b = (const float*)d_in[6];
    const float* W1   = (const float*)d_in[7];
    const float* b1   = (const float*)d_in[8];
    const float* W2   = (const float*)d_in[9];
    const float* b2   = (const float*)d_in[10];
    float* out = (float*)d_out;

    float *xB, *xD, *states, *yln, *h, *carry;
    cudaGetSymbolAddress((void**)&xB,     g_xB);
    cudaGetSymbolAddress((void**)&xD,     g_xD);
    cudaGetSymbolAddress((void**)&states, g_states);
    cudaGetSymbolAddress((void**)&yln,    g_yln);
    cudaGetSymbolAddress((void**)&h,      g_h);
    cudaGetSymbolAddress((void**)&carry,  g_carry);

    cudaFuncSetAttribute(gemm_h3_kernel,
                         cudaFuncAttributeMaxDynamicSharedMemorySize,
                         GH_DYN_SMEM);
    cudaFuncSetAttribute(pipe_kernel,
                         cudaFuncAttributeMaxDynamicSharedMemorySize,
                         GH_DYN_SMEM);

    float* fsp = (out_size >= MROWS * HID + BSZ * STATE)
                     ? (out + (size_t)MROWS * HID) : nullptr;

    // 1) xB = x @ Bm^T (full, must precede scan chunk 0)
    gemm_h3_kernel<<<dim3(STATE / 128, MROWS / 128), 256, GH_DYN_SMEM>>>(
        x, Bm, xB, MROWS, STATE, HID, nullptr, nullptr, nullptr, 0);

    // 2) pipelined chunks: L_k = scan ck ∥ xD ck ∥ r c(k-1) ∥ ln c(k-2)
    //                           ∥ W1 c(k-3) ∥ W2 c(k-4)
    for (int k = 0; k < NCHUNK + 4; ++k) {
        int cs  = (k < NCHUNK) ? k : -1;
        int cr  = (k - 1 >= 0 && k - 1 < NCHUNK) ? k - 1 : -1;
        int cl  = (k - 2 >= 0 && k - 2 < NCHUNK) ? k - 2 : -1;
        int cw1 = (k - 3 >= 0 && k - 3 < NCHUNK) ? k - 3 : -1;
        int cw2 = (k - 4 >= 0 && k - 4 < NCHUNK) ? k - 4 : -1;
        pipe_kernel<<<2312, 256, GH_DYN_SMEM>>>(
            x, Amat, Cm, D, ln_w, ln_b, W1, b1, W2, b2, out,
            xB, xD, states, yln, h, carry, fsp,
            cs, cr, cl, cw1, cw2);
    }
}

// round 16
// speedup vs baseline: 1.2224x; 1.2224x over previous
#include <cuda_runtime.h>
#include <cuda_fp16.h>
#include <math.h>
#include <stdint.h>

// ---------------------------------------------------------------------------
// Problem constants
// ---------------------------------------------------------------------------
#define BSZ    8
#define TLEN   2048
#define HID    1024
#define STATE  256
#define FFNDIM 4096
#define MROWS  (BSZ*TLEN)          // 16384
#define CHUNK  256                 // scan steps per pipeline chunk
#define NCHUNK (TLEN / CHUNK)      // 8

// Scratch (device globals: allocation-free rule)
__device__ float g_xB[MROWS*STATE];      //  16 MB
__device__ float g_xD[MROWS*HID];        //  64 MB (becomes r)
__device__ float g_states[MROWS*STATE];  //  16 MB
__device__ float g_yln[MROWS*HID];       //  64 MB
__device__ float g_h[MROWS*FFNDIM];      // 256 MB
__device__ float g_carry[BSZ*STATE];     // scan state carry between chunks

__device__ __forceinline__ float gelu_exact(float v) {
    return 0.5f * v * (1.0f + erff(v * 0.70710678118654752f));
}

__device__ __forceinline__ uint32_t smem_u32(const void* p) {
    uint32_t a;
    asm("{ .reg .u64 t; cvta.to.shared.u64 t, %1; cvt.u32.u64 %0, t; }"
        : "=r"(a) : "l"(p));
    return a;
}

// ---- packed f32x2 helpers --------------------------------------------------
__device__ __forceinline__ uint64_t pk2(float x, float y) {
    uint64_t r;
    asm("mov.b64 %0, {%1, %2};" : "=l"(r) : "f"(x), "f"(y));
    return r;
}
__device__ __forceinline__ void upk2(uint64_t v, float& x, float& y) {
    asm("mov.b64 {%0, %1}, %2;" : "=f"(x), "=f"(y) : "l"(v));
}
__device__ __forceinline__ uint64_t fma2(uint64_t a, uint64_t b, uint64_t c) {
    uint64_t d;
    asm("fma.rn.f32x2 %0, %1, %2, %3;" : "=l"(d) : "l"(a), "l"(b), "l"(c));
    return d;
}

__device__ __forceinline__ void ldsm4(uint32_t addr, uint32_t r[4]) {
    asm volatile("ldmatrix.sync.aligned.m8n8.x4.shared.b16 {%0,%1,%2,%3}, [%4];"
                 : "=r"(r[0]), "=r"(r[1]), "=r"(r[2]), "=r"(r[3]) : "r"(addr));
}

__device__ __forceinline__ void mma16816(float c[4], const uint32_t a[4],
                                         uint32_t b0, uint32_t b1) {
    asm volatile(
        "mma.sync.aligned.m16n8k16.row.col.f32.f16.f16.f32 "
        "{%0,%1,%2,%3}, {%4,%5,%6,%7}, {%8,%9}, {%0,%1,%2,%3};"
        : "+f"(c[0]), "+f"(c[1]), "+f"(c[2]), "+f"(c[3])
        : "r"(a[0]), "r"(a[1]), "r"(a[2]), "r"(a[3]), "r"(b0), "r"(b1));
}

// ---------------------------------------------------------------------------
// fp16-split (3-pass) tensor-core GEMM body (device function; known-good)
// ---------------------------------------------------------------------------
#define GH_STRIDE_B 80
#define GH_TILE_B   (128 * GH_STRIDE_B)
#define GH_AB 0
#define GH_AS (1 * GH_TILE_B)
#define GH_BB (2 * GH_TILE_B)
#define GH_BS (3 * GH_TILE_B)
#define GH_STAGE (4 * GH_TILE_B)
#define GH_DYN_SMEM (2 * GH_STAGE)

__device__ void gemm_dev(
    const float* __restrict__ A, const float* __restrict__ B,
    float* __restrict__ Cmat,
    size_t row0, size_t col0, int N, int K,
    const float* __restrict__ bias, const float* add1,
    const float* add2, int do_gelu)
{
    extern __shared__ char smem[];
    const uint32_t sbase = smem_u32(smem);

    const int tid = threadIdx.x;
    const int w   = tid >> 5;
    const int l   = tid & 31;
    const int Kc  = K >> 5;

    const int rbase = tid >> 3;
    const int c4    = tid & 7;
    const float* Ap = A + (row0 + rbase) * (size_t)K + c4 * 4;
    const float* Bp = B + (col0 + rbase) * (size_t)K + c4 * 4;

    float4 ra[4], rb4[4];
#pragma unroll
    for (int i = 0; i < 4; ++i) {
        ra[i]  = *(const float4*)(Ap + (size_t)(32 * i) * K);
        rb4[i] = *(const float4*)(Bp + (size_t)(32 * i) * K);
    }

    const uint32_t stoff = (uint32_t)rbase * GH_STRIDE_B + (uint32_t)c4 * 8;

#define CVST(sidx)                                                             \
    do {                                                                       \
        char* pAb = smem + (sidx) * GH_STAGE + GH_AB;                          \
        char* pAs = smem + (sidx) * GH_STAGE + GH_AS;                          \
        char* pBb = smem + (sidx) * GH_STAGE + GH_BB;                          \
        char* pBs = smem + (sidx) * GH_STAGE + GH_BS;                          \
        _Pragma("unroll")                                                      \
        for (int i = 0; i < 4; ++i) {                                          \
            uint32_t off = stoff + (uint32_t)i * (32u * GH_STRIDE_B);          \
            union { __half2 h2[2]; uint2 u; } pk;                              \
            __half2 hb0 = __floats2half2_rn(ra[i].x, ra[i].y);                 \
            __half2 hb1 = __floats2half2_rn(ra[i].z, ra[i].w);                 \
            float2 f0 = __half22float2(hb0), f1 = __half22float2(hb1);         \
            pk.h2[0] = hb0; pk.h2[1] = hb1;                                    \
            *(uint2*)(pAb + off) = pk.u;                                       \
            pk.h2[0] = __floats2half2_rn(ra[i].x - f0.x, ra[i].y - f0.y);      \
            pk.h2[1] = __floats2half2_rn(ra[i].z - f1.x, ra[i].w - f1.y);      \
            *(uint2*)(pAs + off) = pk.u;                                       \
            hb0 = __floats2half2_rn(rb4[i].x, rb4[i].y);                       \
            hb1 = __floats2half2_rn(rb4[i].z, rb4[i].w);                       \
            f0 = __half22float2(hb0); f1 = __half22float2(hb1);                \
            pk.h2[0] = hb0; pk.h2[1] = hb1;                                    \
            *(uint2*)(pBb + off) = pk.u;                                       \
            pk.h2[0] = __floats2half2_rn(rb4[i].x - f0.x, rb4[i].y - f0.y);    \
            pk.h2[1] = __floats2half2_rn(rb4[i].z - f1.x, rb4[i].w - f1.y);    \
            *(uint2*)(pBs + off) = pk.u;                                       \
        }                                                                      \
    } while (0)

    CVST(0);
    __syncthreads();

    const int m0 = (w & 3) * 32;
    const int n0 = (w >> 2) * 64;
    const int rA = l & 15;
    const int qA = l >> 4;
    const int rB = (l & 7) | ((l & 16) >> 1);
    const int qB = (l >> 3) & 1;

    float acc[2][8][4];
#pragma unroll
    for (int mi = 0; mi < 2; ++mi)
#pragma unroll
        for (int ni = 0; ni < 8; ++ni)
#pragma unroll
            for (int q = 0; q < 4; ++q) acc[mi][ni][q] = 0.f;

    for (int kt = 0; kt < Kc; ++kt) {
        if (kt + 1 < Kc) {
            const float* Ap2 = Ap + (kt + 1) * 32;
            const float* Bp2 = Bp + (kt + 1) * 32;
#pragma unroll
            for (int i = 0; i < 4; ++i) {
                ra[i]  = *(const float4*)(Ap2 + (size_t)(32 * i) * K);
                rb4[i] = *(const float4*)(Bp2 + (size_t)(32 * i) * K);
            }
        }

        const uint32_t stb = sbase + (uint32_t)(kt & 1) * GH_STAGE;
#pragma unroll
        for (int kk = 0; kk < 2; ++kk) {
            const int q0 = kk * 2;
            uint32_t ab[2][4], as2[2][4], bb[4][4];
            const uint32_t aoff =
                (uint32_t)(m0 + rA) * GH_STRIDE_B + (uint32_t)(q0 + qA) * 16;
            const uint32_t boff =
                (uint32_t)(n0 + rB) * GH_STRIDE_B + (uint32_t)(q0 + qB) * 16;

            ldsm4(stb + GH_AB + aoff, ab[0]);
            ldsm4(stb + GH_AB + aoff + 16u * GH_STRIDE_B, ab[1]);
            ldsm4(stb + GH_AS + aoff, as2[0]);
            ldsm4(stb + GH_AS + aoff + 16u * GH_STRIDE_B, as2[1]);
#pragma unroll
            for (int g = 0; g < 4; ++g)
                ldsm4(stb + GH_BB + boff + (uint32_t)g * (16u * GH_STRIDE_B), bb[g]);

#pragma unroll
            for (int mi = 0; mi < 2; ++mi)
#pragma unroll
                for (int g = 0; g < 4; ++g) {
                    mma16816(acc[mi][2 * g],     ab[mi], bb[g][0], bb[g][1]);
                    mma16816(acc[mi][2 * g + 1], ab[mi], bb[g][2], bb[g][3]);
                }
#pragma unroll
            for (int mi = 0; mi < 2; ++mi)
#pragma unroll
                for (int g = 0; g < 4; ++g) {
                    mma16816(acc[mi][2 * g],     as2[mi], bb[g][0], bb[g][1]);
                    mma16816(acc[mi][2 * g + 1], as2[mi], bb[g][2], bb[g][3]);
                }
#pragma unroll
            for (int g = 0; g < 4; ++g)
                ldsm4(stb + GH_BS + boff + (uint32_t)g * (16u * GH_STRIDE_B), bb[g]);
#pragma unroll
            for (int mi = 0; mi < 2; ++mi)
#pragma unroll
                for (int g = 0; g < 4; ++g) {
                    mma16816(acc[mi][2 * g],     ab[mi], bb[g][0], bb[g][1]);
                    mma16816(acc[mi][2 * g + 1], ab[mi], bb[g][2], bb[g][3]);
                }
        }

        if (kt + 1 < Kc) CVST((kt + 1) & 1);
        __syncthreads();
    }
#undef CVST

#pragma unroll
    for (int mi = 0; mi < 2; ++mi) {
        const size_t rtop = row0 + m0 + mi * 16 + (l >> 2);
#pragma unroll
        for (int ni = 0; ni < 8; ++ni) {
            const int gc = (int)col0 + n0 + ni * 8 + (l & 3) * 2;
            float bx = 0.f, by = 0.f;
            if (bias) {
                float2 bb2 = *(const float2*)(bias + gc);
                bx = bb2.x; by = bb2.y;
            }
#pragma unroll
            for (int h2i = 0; h2i < 2; ++h2i) {
                const size_t r = rtop + h2i * 8;
                float vx = acc[mi][ni][h2i * 2 + 0] + bx;
                float vy = acc[mi][ni][h2i * 2 + 1] + by;
                if (do_gelu) { vx = gelu_exact(vx); vy = gelu_exact(vy); }
                const size_t idx = r * (size_t)N + gc;
                if (add1) {
                    float2 t = *(const float2*)(add1 + idx);
                    vx += t.x; vy += t.y;
                }
                if (add2) {
                    float2 t = *(const float2*)(add2 + idx);
                    vx += t.x; vy += t.y;
                }
                float2 o; o.x = vx; o.y = vy;
                *(float2*)(Cmat + idx) = o;
            }
        }
    }
}

// Standalone GEMM kernel (used for xB)
__global__ void __launch_bounds__(256, 1) gemm_h3_kernel(
    const float* __restrict__ A, const float* __restrict__ B,
    float* __restrict__ Cmat, int M, int N, int K,
    const float* __restrict__ bias, const float* add1,
    const float* add2, int do_gelu)
{
    gemm_dev(A, B, Cmat, (size_t)blockIdx.y * 128, (size_t)blockIdx.x * 128,
             N, K, bias, add1, add2, do_gelu);
}

// ---------------------------------------------------------------------------
// rLN block: computes r = states@C^T + xD + x for 128 full rows (8 n-tiles),
// then per-row LN stats from the values THIS thread wrote (L2-hot reload,
// identical ownership mapping), then writes yln. No atomics; exact LN.
// ---------------------------------------------------------------------------
#define LN_EPSF 1e-5f

__device__ void r_ln_dev(
    const float* __restrict__ states, const float* __restrict__ Cm,
    const float* __restrict__ x, float* __restrict__ xD,
    const float* __restrict__ lnw, const float* __restrict__ lnb,
    float* __restrict__ yln, size_t row0)
{
    __shared__ float s_sum[2][128];
    __shared__ float s_sq[2][128];

    // 1) r tiles: 8 n-tiles of 128 cols, K=256 (writes r into xD)
    for (int no = 0; no < 8; ++no)
        gemm_dev(states, Cm, xD, row0, (size_t)no * 128, HID, STATE,
                 nullptr, xD, x, 0);

    const int tid = threadIdx.x;
    const int w   = tid >> 5;
    const int l   = tid & 31;
    const int m0  = (w & 3) * 32;
    const int n0  = (w >> 2) * 64;
    const int wg  = w >> 2;

    int rl[4];
#pragma unroll
    for (int s = 0; s < 4; ++s)
        rl[s] = m0 + (s >> 1) * 16 + (l >> 2) + (s & 1) * 8;

    // 2) stats pass (reads back own values)
    float asum[4] = {0.f, 0.f, 0.f, 0.f};
    float asq[4]  = {0.f, 0.f, 0.f, 0.f};
#pragma unroll 1
    for (int no = 0; no < 8; ++no) {
#pragma unroll
        for (int s = 0; s < 4; ++s) {
            const float* rp = xD + (row0 + rl[s]) * (size_t)HID;
#pragma unroll
            for (int nj = 0; nj < 8; ++nj) {
                const int gc = no * 128 + n0 + nj * 8 + (l & 3) * 2;
                float2 v = *(const float2*)(rp + gc);
                asum[s] += v.x + v.y;
                asq[s]  += v.x * v.x + v.y * v.y;
            }
        }
    }
#pragma unroll
    for (int s = 0; s < 4; ++s) {
        asum[s] += __shfl_xor_sync(0xffffffffu, asum[s], 1);
        asum[s] += __shfl_xor_sync(0xffffffffu, asum[s], 2);
        asq[s]  += __shfl_xor_sync(0xffffffffu, asq[s], 1);
        asq[s]  += __shfl_xor_sync(0xffffffffu, asq[s], 2);
    }
    if ((l & 3) == 0) {
#pragma unroll
        for (int s = 0; s < 4; ++s) {
            s_sum[wg][rl[s]] = asum[s];
            s_sq[wg][rl[s]]  = asq[s];
        }
    }
    __syncthreads();

    float fmu[4], finv[4];
#pragma unroll
    for (int s = 0; s < 4; ++s) {
        float S = s_sum[0][rl[s]] + s_sum[1][rl[s]];
        float Q = s_sq[0][rl[s]]  + s_sq[1][rl[s]];
        float mu  = S * (1.0f / HID);
        float var = Q * (1.0f / HID) - mu * mu;
        fmu[s]  = mu;
        finv[s] = rsqrtf(var + LN_EPSF);
    }

    // 3) LN pass: reload own values, normalize, write yln
#pragma unroll 1
    for (int no = 0; no < 8; ++no) {
#pragma unroll
        for (int s = 0; s < 4; ++s) {
            const size_t rb = (row0 + rl[s]) * (size_t)HID;
#pragma unroll
            for (int nj = 0; nj < 8; ++nj) {
                const int gc = no * 128 + n0 + nj * 8 + (l & 3) * 2;
                float2 v  = *(const float2*)(xD + rb + gc);
                float2 wv = *(const float2*)(lnw + gc);
                float2 bv = *(const float2*)(lnb + gc);
                float2 o;
                o.x = (v.x - fmu[s]) * finv[s] * wv.x + bv.x;
                o.y = (v.y - fmu[s]) * finv[s] * wv.y + bv.y;
                *(float2*)(yln + rb + gc) = o;
            }
        }
    }
}

// ---------------------------------------------------------------------------
// Scan chunk (device): one block per batch, 256 threads, CHUNK steps.
// (byte-identical to R13 — known-good)
// ---------------------------------------------------------------------------
#define SC_AREG   208
#define SC_ASM    12
#define SC_ASM_B  (SC_ASM * 256 * 16)
#define SC_ST_B   (2 * 256 * 4)
#define SC_XB_B   (2 * 8 * 256 * 4)
#define SC_SMEM_BYTES (SC_ASM_B + SC_ST_B + SC_XB_B)

__device__ void scan_chunk_dev(
    const float* __restrict__ Amat,
    const float* __restrict__ xB,
    float* __restrict__ states,
    float* __restrict__ carry,
    float* fs_out,
    int b, int c)
{
    extern __shared__ char ssm[];
    float4* Atail = (float4*)ssm;
    float*  st    = (float*)(ssm + SC_ASM_B);
    float*  xbsm  = (float*)(ssm + SC_ASM_B + SC_ST_B);

    const int tid = threadIdx.x;

    const float* arow = Amat + tid * STATE;
    uint64_t areg[SC_AREG / 2];
#pragma unroll
    for (int q = 0; q < SC_AREG / 4; ++q) {
        float4 a4 = *(const float4*)(arow + 4 * q);
        areg[2 * q]     = pk2(a4.x, a4.y);
        areg[2 * q + 1] = pk2(a4.z, a4.w);
    }
#pragma unroll
    for (int q = 0; q < SC_ASM; ++q)
        Atail[q * 256 + tid] = *(const float4*)(arow + SC_AREG + 4 * q);

    st[tid]       = (c == 0) ? 0.f : carry[b * STATE + tid];
    st[256 + tid] = 0.f;

    const float* xbbase =
        xB + (size_t)b * TLEN * STATE + (size_t)c * CHUNK * STATE;
    const int s0 = tid >> 6, c0 = (tid & 63) * 4;
    const int s1 = 4 + s0;
    float4 pf0 = *(const float4*)(xbbase + (size_t)s0 * STATE + c0);
    float4 pf1 = *(const float4*)(xbbase + (size_t)s1 * STATE + c0);
    *(float4*)(xbsm + s0 * 256 + c0) = pf0;
    *(float4*)(xbsm + s1 * 256 + c0) = pf1;

    float* sbp = states + (size_t)b * TLEN * STATE +
                 (size_t)c * CHUNK * STATE + tid;
    __syncthreads();

    float ttlast = 0.f;
    for (int t = 0; t < CHUNK; ++t) {
        const int buf  = t & 1;
        const int nbuf = buf ^ 1;

        const float xc = xbsm[((t >> 3) & 1) * 2048 + (t & 7) * 256 + tid];

        const float4* sp = (const float4*)(st + buf * 256);
        uint64_t a0 = pk2(0.f, 0.f), a1 = pk2(0.f, 0.f);
        uint64_t a2 = pk2(0.f, 0.f), a3 = pk2(0.f, 0.f);
#pragma unroll
        for (int q = 0; q < SC_AREG / 4; ++q) {
            float4 s4 = sp[q];
            if (q & 1) {
                a2 = fma2(areg[2 * q],     pk2(s4.x, s4.y), a2);
                a3 = fma2(areg[2 * q + 1], pk2(s4.z, s4.w), a3);
            } else {
                a0 = fma2(areg[2 * q],     pk2(s4.x, s4.y), a0);
                a1 = fma2(areg[2 * q + 1], pk2(s4.z, s4.w), a1);
            }
        }
#pragma unroll
        for (int q = 0; q < SC_ASM; ++q) {
            float4 s4 = sp[SC_AREG / 4 + q];
            float4 a4 = Atail[q * 256 + tid];
            if (q & 1) {
                a2 = fma2(pk2(a4.x, a4.y), pk2(s4.x, s4.y), a2);
                a3 = fma2(pk2(a4.z, a4.w), pk2(s4.z, s4.w), a3);
            } else {
                a0 = fma2(pk2(a4.x, a4.y), pk2(s4.x, s4.y), a0);
                a1 = fma2(pk2(a4.z, a4.w), pk2(s4.z, s4.w), a1);
            }
        }
        float l0, h0, l1, h1, l2, h2, l3, h3;
        upk2(a0, l0, h0); upk2(a1, l1, h1);
        upk2(a2, l2, h2); upk2(a3, l3, h3);
        float v = ((l0 + h0) + (l1 + h1)) + ((l2 + h2) + (l3 + h3)) + xc;

        float ax = fabsf(v);
        float e  = __expf(2.0f * ax);
        float tt = copysignf(1.0f - __fdividef(2.0f, e + 1.0f), v);

        st[nbuf * 256 + tid] = tt;
        sbp[(size_t)t * STATE] = tt;
        ttlast = tt;

        if (t < CHUNK - 8) {
            const int ph = t & 7;
            if (ph == 1) {
                const size_t base = ((size_t)(t >> 3) + 1) * 8;
                pf0 = *(const float4*)(xbbase + (base + s0) * STATE + c0);
                pf1 = *(const float4*)(xbbase + (base + s1) * STATE + c0);
            } else if (ph == 6) {
                const int cb = (((t >> 3) + 1) & 1) * 2048;
                *(float4*)(xbsm + cb + s0 * 256 + c0) = pf0;
                *(float4*)(xbsm + cb + s1 * 256 + c0) = pf1;
            }
        }

        __syncthreads();
    }

    carry[b * STATE + tid] = ttlast;
    if (c == NCHUNK - 1 && fs_out != nullptr)
        fs_out[b * STATE + tid] = ttlast;
}

// ---------------------------------------------------------------------------
// Union pipeline kernel. Grid = 792:
//   [0,8)      scan chunk c_scan (batch = bid)
//   [8,136)    xD tiles for c_scan               (128)
//   [136,152)  rLN blocks (128 rows each), c_r   (16)
//   [152,664)  W1 gelu tiles, c_w1               (512)
//   [664,792)  W2 tiles, c_w2                    (128)
// Row base of m-tile `my` in chunk c: (my>>1)*TLEN + c*CHUNK + (my&1)*128
// ---------------------------------------------------------------------------
__device__ __forceinline__ size_t prow0(int c, int my) {
    return (size_t)(my >> 1) * TLEN + (size_t)c * CHUNK + (size_t)(my & 1) * 128;
}

__global__ void __launch_bounds__(256, 1) pipe_kernel(
    const float* __restrict__ x, const float* __restrict__ Amat,
    const float* __restrict__ Cm, const float* __restrict__ D,
    const float* __restrict__ ln_w, const float* __restrict__ ln_b,
    const float* __restrict__ W1, const float* __restrict__ b1,
    const float* __restrict__ W2, const float* __restrict__ b2,
    float* __restrict__ out,
    float* xB, float* xD, float* states, float* yln, float* h,
    float* carry, float* fsp,
    int c_scan, int c_r, int c_w1, int c_w2)
{
    int bid = blockIdx.x;

    if (bid < 8) {
        if (c_scan >= 0)
            scan_chunk_dev(Amat, xB, states, carry, fsp, bid, c_scan);
        return;
    }
    bid -= 8;
    if (bid < 128) {                       // xD = x @ D^T (chunk rows)
        if (c_scan >= 0)
            gemm_dev(x, D, xD, prow0(c_scan, bid >> 3),
                     (size_t)(bid & 7) * 128, HID, HID,
                     nullptr, nullptr, nullptr, 0);
        return;
    }
    bid -= 128;
    if (bid < 16) {                        // rLN: r + LayerNorm, 128 rows
        if (c_r >= 0)
            r_ln_dev(states, Cm, x, xD, ln_w, ln_b, yln,
                     prow0(c_r, bid));
        return;
    }
    bid -= 16;
    if (bid < 512) {                       // h = gelu(yln @ W1^T + b1)
        if (c_w1 >= 0)
            gemm_dev(yln, W1, h, prow0(c_w1, bid >> 5),
                     (size_t)(bid & 31) * 128, FFNDIM, HID,
                     b1, nullptr, nullptr, 1);
        return;
    }
    bid -= 512;
    {                                      // y = yln + h @ W2^T + b2
        if (c_w2 >= 0)
            gemm_dev(h, W2, out, prow0(c_w2, bid >> 3),
                     (size_t)(bid & 7) * 128, HID, FFNDIM,
                     b2, yln, nullptr, 0);
    }
}

// ---------------------------------------------------------------------------
// Launch: xB GEMM, then NCHUNK+3 = 11 pipelined union launches.
// ---------------------------------------------------------------------------
extern "C" void kernel_launch(void* const* d_in, const int* in_sizes, int n_in,
                              void* d_out, int out_size)
{
    const float* x    = (const float*)d_in[0];
    const float* Amat = (const float*)d_in[1];
    const float* Bm   = (const float*)d_in[2];
    const float* Cm   = (const float*)d_in[3];
    const float* D    = (const float*)d_in[4];
    const float* ln_w = (const float*)d_in[5];
    const float* ln_b = (const float*)d_in[6];
    const float* W1   = (const float*)d_in[7];
    const float* b1   = (const float*)d_in[8];
    const float* W2   = (const float*)d_in[9];
    const float* b2   = (const float*)d_in[10];
    float* out = (float*)d_out;

    float *xB, *xD, *states, *yln, *h, *carry;
    cudaGetSymbolAddress((void**)&xB,     g_xB);
    cudaGetSymbolAddress((void**)&xD,     g_xD);
    cudaGetSymbolAddress((void**)&states, g_states);
    cudaGetSymbolAddress((void**)&yln,    g_yln);
    cudaGetSymbolAddress((void**)&h,      g_h);
    cudaGetSymbolAddress((void**)&carry,  g_carry);

    cudaFuncSetAttribute(gemm_h3_kernel,
                         cudaFuncAttributeMaxDynamicSharedMemorySize,
                         GH_DYN_SMEM);
    cudaFuncSetAttribute(pipe_kernel,
                         cudaFuncAttributeMaxDynamicSharedMemorySize,
                         GH_DYN_SMEM);

    float* fsp = (out_size >= MROWS * HID + BSZ * STATE)
                     ? (out + (size_t)MROWS * HID) : nullptr;

    // 1) xB = x @ Bm^T (full, must precede scan chunk 0)
    gemm_h3_kernel<<<dim3(STATE / 128, MROWS / 128), 256, GH_DYN_SMEM>>>(
        x, Bm, xB, MROWS, STATE, HID, nullptr, nullptr, nullptr, 0);

    // 2) pipelined chunks: L_k = scan ck ∥ xD ck ∥ rLN c(k-1)
    //                           ∥ W1 c(k-2) ∥ W2 c(k-3)
    for (int k = 0; k < NCHUNK + 3; ++k) {
        int cs  = (k < NCHUNK) ? k : -1;
        int cr  = (k - 1 >= 0 && k - 1 < NCHUNK) ? k - 1 : -1;
        int cw1 = (k - 2 >= 0 && k - 2 < NCHUNK) ? k - 2 : -1;
        int cw2 = (k - 3 >= 0 && k - 3 < NCHUNK) ? k - 3 : -1;
        pipe_kernel<<<792, 256, GH_DYN_SMEM>>>(
            x, Amat, Cm, D, ln_w, ln_b, W1, b1, W2, b2, out,
            xB, xD, states, yln, h, carry, fsp,
            cs, cr, cw1, cw2);
    }
}